// round 1
// baseline (speedup 1.0000x reference)
#include <cuda_runtime.h>
#include <math.h>

// Problem constants (fixed by the reference)
#define NN    1536   // nodes
#define DEG   32     // candidate out-degree per node
#define BS    8      // sequential batch steps
#define OBSD  33
#define HIDN  64
#define NH    4      // heads
#define CD    8      // channels per head
#define KS    4      // top-k
#define EMB   32
#define ATTN_OFS ((size_t)BS * NN * EMB)   // outs precede attns in d_out

// -------- persistent device scratch (no allocations allowed) --------
__device__ float g_Hemb[BS * NN * EMB];
__device__ float g_h[2][NN * HIDN];
__device__ float g_P[NN * HIDN];
__device__ float g_Q[NN * HIDN];
__device__ float g_xh[NN * EMB];
__device__ float g_as[NN * NH];
__device__ float g_ad[NN * NH];
__device__ int   g_kdst[NN * KS];
__device__ float g_kw[NN * KS];
__device__ float g_klog[NN * KS * NH];
__device__ float g_kex[NN * KS * NH];
__device__ float g_m[NN * NH];
__device__ float g_ssum[NN * NH];

__device__ __forceinline__ float sigm(float x) { return 1.f / (1.f + expf(-x)); }

__device__ __forceinline__ void atomicMaxF(float* addr, float val) {
    int* ia = (int*)addr;
    int old = *ia;
    while (__int_as_float(old) < val) {
        int assumed = old;
        old = atomicCAS(ia, assumed, __float_as_int(val));
        if (old == assumed) break;
    }
}

// ---------------- Obs embedding: Linear-ReLU-Linear-ReLU-LayerNorm ----------------
// grid = B*N blocks, 32 threads (one warp) each.
__global__ void embed_k(const float* __restrict__ Ht,
                        const float* __restrict__ We1, const float* __restrict__ be1,
                        const float* __restrict__ We2, const float* __restrict__ be2,
                        const float* __restrict__ lng, const float* __restrict__ lnb) {
    int bn = blockIdx.x;
    int j  = threadIdx.x;  // 0..31
    __shared__ float sh[OBSD];
    __shared__ float x1[EMB];
    const float* row = Ht + (size_t)bn * OBSD;
    sh[j] = row[j];
    if (j == 0) sh[32] = row[32];
    __syncwarp();

    float a = be1[j];
#pragma unroll
    for (int k = 0; k < OBSD; k++) a += sh[k] * We1[k * EMB + j];
    a = fmaxf(a, 0.f);
    x1[j] = a;
    __syncwarp();

    float b = be2[j];
#pragma unroll
    for (int k = 0; k < EMB; k++) b += x1[k] * We2[k * EMB + j];
    b = fmaxf(b, 0.f);

    // LayerNorm over 32 (single warp)
    float s = b;
#pragma unroll
    for (int o = 16; o; o >>= 1) s += __shfl_xor_sync(0xffffffffu, s, o);
    float mu = s * (1.f / 32.f);
    float d  = b - mu;
    float v  = d * d;
#pragma unroll
    for (int o = 16; o; o >>= 1) v += __shfl_xor_sync(0xffffffffu, v, o);
    float var = v * (1.f / 32.f);
    g_Hemb[(size_t)bn * EMB + j] = d * rsqrtf(var + 1e-5f) * lng[j] + lnb[j];
}

// ---------------- K1: GRU cell + per-node precompute + per-step inits ----------------
// grid = N blocks, 64 threads.
__global__ void k1_node(int step,
                        const float* __restrict__ Wih, const float* __restrict__ Whh,
                        const float* __restrict__ bih, const float* __restrict__ bhh,
                        const float* __restrict__ Ws1, const float* __restrict__ bs1,
                        const float* __restrict__ Wgat,
                        const float* __restrict__ asrc, const float* __restrict__ adst,
                        const float* __restrict__ bgat,
                        float* __restrict__ outp) {
    int n = blockIdx.x, j = threadIdx.x;  // j: 0..63
    __shared__ float e_s[EMB], h_s[HIDN], hn_s[HIDN], xh_s[EMB];

    if (j < EMB) e_s[j] = g_Hemb[((size_t)step * NN + n) * EMB + j];
    float hold = (step == 0) ? 0.f : g_h[step & 1][n * HIDN + j];
    h_s[j] = hold;
    __syncthreads();

    float gi[3], gh[3];
#pragma unroll
    for (int g = 0; g < 3; g++) {
        const float* wr = Wih + (g * HIDN + j) * EMB;
        float aa = bih[g * HIDN + j];
#pragma unroll
        for (int k = 0; k < EMB; k++) aa += e_s[k] * wr[k];
        gi[g] = aa;
        const float* wr2 = Whh + (g * HIDN + j) * HIDN;
        float bb = bhh[g * HIDN + j];
#pragma unroll 8
        for (int k = 0; k < HIDN; k++) bb += h_s[k] * wr2[k];
        gh[g] = bb;
    }
    float r  = sigm(gi[0] + gh[0]);
    float z  = sigm(gi[1] + gh[1]);
    float nn = tanhf(gi[2] + r * gh[2]);
    float hn = (1.f - z) * nn + z * hold;
    hn_s[j] = hn;
    g_h[(step + 1) & 1][n * HIDN + j] = hn;
    __syncthreads();

    // P = h@Ws1[:64] + b_s1 ; Q = h@Ws1[64:]
    float p = bs1[j], q = 0.f;
#pragma unroll 8
    for (int k = 0; k < HIDN; k++) {
        p += hn_s[k] * Ws1[k * HIDN + j];
        q += hn_s[k] * Ws1[(HIDN + k) * HIDN + j];
    }
    g_P[n * HIDN + j] = p;
    g_Q[n * HIDN + j] = q;

    if (j < EMB) {
        float x = 0.f;
#pragma unroll 8
        for (int k = 0; k < HIDN; k++) x += hn_s[k] * Wgat[k * EMB + j];
        xh_s[j] = x;
        g_xh[n * EMB + j] = x;
        outp[((size_t)step * NN + n) * EMB + j] = bgat[j];  // segment_sum init + bias
    }
    __syncthreads();

    if (j < NH) {
        float as_ = 0.f, ad_ = 0.f;
#pragma unroll
        for (int c = 0; c < CD; c++) {
            as_ += xh_s[j * CD + c] * asrc[j * CD + c];
            ad_ += xh_s[j * CD + c] * adst[j * CD + c];
        }
        g_as[n * NH + j] = as_;
        g_ad[n * NH + j] = ad_;
        g_m[n * NH + j]    = -INFINITY;  // segment max init
        g_ssum[n * NH + j] = 0.f;        // segment sum init
    }
}

// ---------------- K2: edge scores + warp top-k + segment max ----------------
// grid = N blocks (one per src), 32 threads (one per candidate edge).
__global__ void k2_edge(const int* __restrict__ dst,
                        const float* __restrict__ Ws2, const float* __restrict__ bs2) {
    int n = blockIdx.x, lane = threadIdx.x;
    __shared__ float P_s[HIDN];
    __shared__ float w2_s[HIDN];
    P_s[lane]       = g_P[n * HIDN + lane];
    P_s[32 + lane]  = g_P[n * HIDN + 32 + lane];
    w2_s[lane]      = Ws2[lane];
    w2_s[32 + lane] = Ws2[32 + lane];
    __syncwarp();

    int d = dst[n * DEG + lane];
    const float* Qr = g_Q + (size_t)d * HIDN;
    float acc = bs2[0];
#pragma unroll 8
    for (int k = 0; k < HIDN; k++) acc += fmaxf(P_s[k] + Qr[k], 0.f) * w2_s[k];
    float score = sigm(acc);

    // top-k (k=4) among the 32 lanes; ties -> lower index (matches jax.lax.top_k)
    bool sel = false;
#pragma unroll
    for (int r = 0; r < KS; r++) {
        float v = sel ? -1e30f : score;
        int   idx = lane;
#pragma unroll
        for (int o = 16; o; o >>= 1) {
            float ov = __shfl_xor_sync(0xffffffffu, v, o);
            int   oi = __shfl_xor_sync(0xffffffffu, idx, o);
            if (ov > v || (ov == v && oi < idx)) { v = ov; idx = oi; }
        }
        if (lane == idx) sel = true;
    }
    unsigned ball = __ballot_sync(0xffffffffu, sel);
    if (sel) {
        int slot = __popc(ball & ((1u << lane) - 1u));
        g_kdst[n * KS + slot] = d;
        g_kw[n * KS + slot]   = score;
#pragma unroll
        for (int h = 0; h < NH; h++) {
            float lg = g_as[n * NH + h] + g_ad[d * NH + h];
            lg = lg > 0.f ? lg : 0.2f * lg;  // leaky_relu(0.2)
            g_klog[(n * KS + slot) * NH + h] = lg;
            atomicMaxF(&g_m[d * NH + h], lg);
        }
    }
}

// ---------------- K3: exp(logit - m) and segment sums ----------------
__global__ void k3_exp() {
    int gid = blockIdx.x * blockDim.x + threadIdx.x;
    if (gid >= NN * KS * NH) return;
    int h = gid & 3, i = (gid >> 2) & 3, n = gid >> 4;
    int d = g_kdst[n * KS + i];
    float ex = expf(g_klog[(n * KS + i) * NH + h] - g_m[d * NH + h]);
    g_kex[(n * KS + i) * NH + h] = ex;
    atomicAdd(&g_ssum[d * NH + h], ex);
}

// ---------------- K4: alpha, A row streaming write (zeros + scatter), out msgs ----------------
// grid = N blocks (one per src row), 128 threads.
__global__ void k4_final(int step, float* __restrict__ outp) {
    int n = blockIdx.x, tid = threadIdx.x;
    __shared__ float alpha_s[KS][NH];
    __shared__ int   d_s[KS];
    __shared__ float w_s[KS];
    __shared__ float rinv[NH];

    if (tid < 16) {
        int i = tid >> 2, h = tid & 3;
        int d = g_kdst[n * KS + i];
        if (h == 0) { d_s[i] = d; w_s[i] = g_kw[n * KS + i]; }
        alpha_s[i][h] = g_kex[(n * KS + i) * NH + h] / fmaxf(g_ssum[d * NH + h], 1e-16f);
    }
    __syncthreads();
    if (tid < NH) {
        float rs = alpha_s[0][tid] + alpha_s[1][tid] + alpha_s[2][tid] + alpha_s[3][tid];
        rinv[tid] = 1.f / fmaxf(rs, 1e-9f);
    }
    __syncthreads();

    // Stream-zero the 4 head-rows A[step, h, n, :] (block exclusively owns them).
    float* Abase = outp + ATTN_OFS;
    float4 z4 = make_float4(0.f, 0.f, 0.f, 0.f);
#pragma unroll
    for (int h = 0; h < NH; h++) {
        float4* row = (float4*)(Abase + (((size_t)step * NH + h) * NN + n) * NN);
        for (int idx = tid; idx < NN / 4; idx += 128) row[idx] = z4;
    }
    __syncthreads();

    // Scatter normalized alphas (handle duplicate dst within the 4 kept edges).
    if (tid < 16) {
        int i = tid >> 2, h = tid & 3;
        int d = d_s[i];
        bool first = true;
        for (int j = 0; j < i; j++) if (d_s[j] == d) first = false;
        if (first) {
            float a = alpha_s[i][h];
            for (int j = i + 1; j < KS; j++) if (d_s[j] == d) a += alpha_s[j][h];
            Abase[(((size_t)step * NH + h) * NN + n) * NN + d] = a * rinv[h];
        }
    }

    // Out messages: 128 threads = 4 edges x 4 heads x 8 channels
    {
        int i = tid >> 5, h = (tid >> 3) & 3, c = tid & 7;
        float val = alpha_s[i][h] * g_xh[n * EMB + h * CD + c] * w_s[i];
        atomicAdd(&outp[((size_t)step * NN + d_s[i]) * EMB + h * CD + c], val);
    }
}

// ---------------- launch ----------------
extern "C" void kernel_launch(void* const* d_in, const int* in_sizes, int n_in,
                              void* d_out, int out_size) {
    // inputs: H_t, src, dst, [k], W_e1, b_e1, W_e2, b_e2, ln_g, ln_b,
    //         W_ih, W_hh, b_ih, b_hh, W_s1, b_s1, W_s2, b_s2,
    //         W_gat, att_src, att_dst, b_gat
    int base = (in_sizes[3] == 1) ? 4 : 3;  // scalar k may or may not be materialized
    const float* Ht  = (const float*)d_in[0];
    const int*   dst = (const int*)d_in[2];
    const float* We1 = (const float*)d_in[base + 0];
    const float* be1 = (const float*)d_in[base + 1];
    const float* We2 = (const float*)d_in[base + 2];
    const float* be2 = (const float*)d_in[base + 3];
    const float* lng = (const float*)d_in[base + 4];
    const float* lnb = (const float*)d_in[base + 5];
    const float* Wih = (const float*)d_in[base + 6];
    const float* Whh = (const float*)d_in[base + 7];
    const float* bih = (const float*)d_in[base + 8];
    const float* bhh = (const float*)d_in[base + 9];
    const float* Ws1 = (const float*)d_in[base + 10];
    const float* bs1 = (const float*)d_in[base + 11];
    const float* Ws2 = (const float*)d_in[base + 12];
    const float* bs2 = (const float*)d_in[base + 13];
    const float* Wgat = (const float*)d_in[base + 14];
    const float* asrc = (const float*)d_in[base + 15];
    const float* adst = (const float*)d_in[base + 16];
    const float* bgat = (const float*)d_in[base + 17];
    float* outp = (float*)d_out;

    embed_k<<<BS * NN, 32>>>(Ht, We1, be1, We2, be2, lng, lnb);
    for (int t = 0; t < BS; t++) {
        k1_node<<<NN, 64>>>(t, Wih, Whh, bih, bhh, Ws1, bs1, Wgat, asrc, adst, bgat, outp);
        k2_edge<<<NN, 32>>>(dst, Ws2, bs2);
        k3_exp<<<(NN * KS * NH + 127) / 128, 128>>>();
        k4_final<<<NN, 128>>>(t, outp);
    }
}

// round 3
// speedup vs baseline: 4.1192x; 4.1192x over previous
#include <cuda_runtime.h>
#include <math.h>

// Problem constants (fixed by the reference)
#define NN    1536   // nodes
#define DEG   32     // candidate out-degree per node
#define BS    8      // sequential batch steps
#define OBSD  33
#define HIDN  64
#define NH    4      // heads
#define CD    8      // channels per head
#define KS    4      // top-k
#define EMB   32
#define ATTN_OFS ((size_t)BS * NN * EMB)   // outs precede attns in d_out

#define NTB 4   // nodes per block in k1
#define RTB 8   // rows per block in embed

// -------- persistent device scratch (no allocations allowed) --------
__device__ float g_Hemb[BS * NN * EMB];
__device__ float g_h[NN * HIDN];
__device__ float g_P[NN * HIDN];
__device__ float g_Q[NN * HIDN];
__device__ float g_xh[NN * EMB];
__device__ float g_as[NN * NH];
__device__ float g_ad[NN * NH];
__device__ int   g_kdst[NN * KS];
__device__ float g_kw[NN * KS];
__device__ float g_kex[NN * KS * NH];
__device__ float g_ssum[NN * NH];
__device__ float g_Aval[BS * NN * KS * NH];  // normalized, dedup-merged A entries
__device__ int   g_Adst[BS * NN * KS];       // -1 = duplicate slot (skip)

__device__ __forceinline__ float sigm(float x) { return 1.f / (1.f + expf(-x)); }

// ---------------- Obs embedding: Linear-ReLU-Linear-ReLU-LayerNorm ----------------
// grid = B*N/RTB blocks, 32 threads; each thread computes channel j for RTB rows.
__global__ void embed_k(const float* __restrict__ Ht,
                        const float* __restrict__ We1, const float* __restrict__ be1,
                        const float* __restrict__ We2, const float* __restrict__ be2,
                        const float* __restrict__ lng, const float* __restrict__ lnb) {
    int r0 = blockIdx.x * RTB;
    int j  = threadIdx.x;  // 0..31
    __shared__ float in_s[RTB][OBSD + 1];
    __shared__ float x1_s[RTB][EMB];

    for (int t = j; t < RTB * OBSD; t += 32)
        in_s[t / OBSD][t % OBSD] = Ht[(size_t)r0 * OBSD + t];
    __syncwarp();

    float a[RTB];
    float b1 = be1[j];
#pragma unroll
    for (int m = 0; m < RTB; m++) a[m] = b1;
#pragma unroll
    for (int k = 0; k < OBSD; k++) {
        float w = We1[k * EMB + j];
#pragma unroll
        for (int m = 0; m < RTB; m++) a[m] += in_s[m][k] * w;
    }
#pragma unroll
    for (int m = 0; m < RTB; m++) x1_s[m][j] = fmaxf(a[m], 0.f);
    __syncwarp();

    float b[RTB];
    float b2 = be2[j];
#pragma unroll
    for (int m = 0; m < RTB; m++) b[m] = b2;
#pragma unroll
    for (int k = 0; k < EMB; k++) {
        float w = We2[k * EMB + j];
#pragma unroll
        for (int m = 0; m < RTB; m++) b[m] += x1_s[m][k] * w;
    }

    float gj = lng[j], bj = lnb[j];
#pragma unroll
    for (int m = 0; m < RTB; m++) {
        float x = fmaxf(b[m], 0.f);
        float s = x;
#pragma unroll
        for (int o = 16; o; o >>= 1) s += __shfl_xor_sync(0xffffffffu, s, o);
        float mu = s * (1.f / 32.f);
        float d  = x - mu;
        float v  = d * d;
#pragma unroll
        for (int o = 16; o; o >>= 1) v += __shfl_xor_sync(0xffffffffu, v, o);
        g_Hemb[(size_t)(r0 + m) * EMB + j] = d * rsqrtf(v * (1.f / 32.f) + 1e-5f) * gj + bj;
    }
}

// ---------------- K1: GRU + per-node precompute + per-step inits ----------------
// grid = N/NTB blocks, 64 threads; each thread computes output j for NTB nodes.
__global__ void k1_node(int step,
                        const float* __restrict__ Wih, const float* __restrict__ Whh,
                        const float* __restrict__ bih, const float* __restrict__ bhh,
                        const float* __restrict__ Ws1, const float* __restrict__ bs1,
                        const float* __restrict__ Wgat,
                        const float* __restrict__ asrc, const float* __restrict__ adst,
                        const float* __restrict__ bgat,
                        float* __restrict__ outp) {
    int n0 = blockIdx.x * NTB;
    int j  = threadIdx.x;  // 0..63
    __shared__ float e_s[NTB][EMB];
    __shared__ float h_s[NTB][HIDN];
    __shared__ float hn_s[NTB][HIDN];
    __shared__ float xh_s[NTB][EMB];

    for (int t = j; t < NTB * EMB; t += 64)
        e_s[t >> 5][t & 31] = g_Hemb[((size_t)step * NN + n0) * EMB + t];
    for (int t = j; t < NTB * HIDN; t += 64)
        h_s[t >> 6][t & 63] = (step == 0) ? 0.f : g_h[(size_t)n0 * HIDN + t];
    __syncthreads();

    float rg[NTB], zg[NTB], hn[NTB];
#pragma unroll
    for (int g = 0; g < 3; g++) {
        float bi = bih[g * HIDN + j];
        float bh = bhh[g * HIDN + j];
        float ai[NTB], ah[NTB];
#pragma unroll
        for (int m = 0; m < NTB; m++) { ai[m] = bi; ah[m] = bh; }
        const float4* wi = (const float4*)(Wih + (size_t)(g * HIDN + j) * EMB);
#pragma unroll
        for (int k4 = 0; k4 < EMB / 4; k4++) {
            float4 w = wi[k4];
            int k = k4 * 4;
#pragma unroll
            for (int m = 0; m < NTB; m++)
                ai[m] += e_s[m][k] * w.x + e_s[m][k + 1] * w.y + e_s[m][k + 2] * w.z + e_s[m][k + 3] * w.w;
        }
        const float4* wh = (const float4*)(Whh + (size_t)(g * HIDN + j) * HIDN);
#pragma unroll
        for (int k4 = 0; k4 < HIDN / 4; k4++) {
            float4 w = wh[k4];
            int k = k4 * 4;
#pragma unroll
            for (int m = 0; m < NTB; m++)
                ah[m] += h_s[m][k] * w.x + h_s[m][k + 1] * w.y + h_s[m][k + 2] * w.z + h_s[m][k + 3] * w.w;
        }
        if (g == 0) {
#pragma unroll
            for (int m = 0; m < NTB; m++) rg[m] = sigm(ai[m] + ah[m]);
        } else if (g == 1) {
#pragma unroll
            for (int m = 0; m < NTB; m++) zg[m] = sigm(ai[m] + ah[m]);
        } else {
#pragma unroll
            for (int m = 0; m < NTB; m++) {
                float nv = tanhf(ai[m] + rg[m] * ah[m]);
                hn[m] = (1.f - zg[m]) * nv + zg[m] * h_s[m][j];
            }
        }
    }
#pragma unroll
    for (int m = 0; m < NTB; m++) {
        hn_s[m][j] = hn[m];
        g_h[(size_t)(n0 + m) * HIDN + j] = hn[m];
    }
    __syncthreads();

    // P = h@Ws1[:64] + b_s1 ; Q = h@Ws1[64:]
    float p[NTB], q[NTB];
    float bp = bs1[j];
#pragma unroll
    for (int m = 0; m < NTB; m++) { p[m] = bp; q[m] = 0.f; }
#pragma unroll 8
    for (int k = 0; k < HIDN; k++) {
        float w1 = Ws1[k * HIDN + j];
        float w2 = Ws1[(HIDN + k) * HIDN + j];
#pragma unroll
        for (int m = 0; m < NTB; m++) { p[m] += hn_s[m][k] * w1; q[m] += hn_s[m][k] * w2; }
    }
#pragma unroll
    for (int m = 0; m < NTB; m++) {
        g_P[(size_t)(n0 + m) * HIDN + j] = p[m];
        g_Q[(size_t)(n0 + m) * HIDN + j] = q[m];
    }

    if (j < EMB) {
        float x[NTB];
#pragma unroll
        for (int m = 0; m < NTB; m++) x[m] = 0.f;
#pragma unroll 8
        for (int k = 0; k < HIDN; k++) {
            float w = Wgat[k * EMB + j];
#pragma unroll
            for (int m = 0; m < NTB; m++) x[m] += hn_s[m][k] * w;
        }
        float bg = bgat[j];
#pragma unroll
        for (int m = 0; m < NTB; m++) {
            xh_s[m][j] = x[m];
            g_xh[(size_t)(n0 + m) * EMB + j] = x[m];
            outp[((size_t)step * NN + n0 + m) * EMB + j] = bg;  // segment_sum init + bias
        }
    }
    __syncthreads();

    if (j < NTB * NH) {
        int m = j >> 2, h = j & 3;
        float as_ = 0.f, ad_ = 0.f;
#pragma unroll
        for (int c = 0; c < CD; c++) {
            as_ += xh_s[m][h * CD + c] * asrc[h * CD + c];
            ad_ += xh_s[m][h * CD + c] * adst[h * CD + c];
        }
        g_as[(n0 + m) * NH + h]   = as_;
        g_ad[(n0 + m) * NH + h]   = ad_;
        g_ssum[(n0 + m) * NH + h] = 0.f;
    }
}

// ---------------- K2: edge scores + warp top-k + exp + segment sums ----------------
// grid = N blocks (one per src), 32 threads (one per candidate edge).
__global__ void k2_edge(const int* __restrict__ dst,
                        const float* __restrict__ Ws2, const float* __restrict__ bs2) {
    int n = blockIdx.x, lane = threadIdx.x;
    __shared__ float P_s[HIDN];
    __shared__ float w2_s[HIDN];
    __shared__ float as_s[NH];
    P_s[lane]       = g_P[n * HIDN + lane];
    P_s[32 + lane]  = g_P[n * HIDN + 32 + lane];
    w2_s[lane]      = Ws2[lane];
    w2_s[32 + lane] = Ws2[32 + lane];
    if (lane < NH) as_s[lane] = g_as[n * NH + lane];
    __syncwarp();

    int d = dst[n * DEG + lane];
    const float4* Qr = (const float4*)(g_Q + (size_t)d * HIDN);
    float acc = bs2[0];
#pragma unroll
    for (int k4 = 0; k4 < HIDN / 4; k4++) {
        float4 qv = Qr[k4];
        int k = k4 * 4;
        acc += fmaxf(P_s[k] + qv.x, 0.f) * w2_s[k]
             + fmaxf(P_s[k + 1] + qv.y, 0.f) * w2_s[k + 1]
             + fmaxf(P_s[k + 2] + qv.z, 0.f) * w2_s[k + 2]
             + fmaxf(P_s[k + 3] + qv.w, 0.f) * w2_s[k + 3];
    }
    float score = sigm(acc);

    // top-k (k=4) among the 32 lanes; ties -> lower index (matches jax.lax.top_k)
    bool sel = false;
#pragma unroll
    for (int r = 0; r < KS; r++) {
        float v = sel ? -1e30f : score;
        int   idx = lane;
#pragma unroll
        for (int o = 16; o; o >>= 1) {
            float ov = __shfl_xor_sync(0xffffffffu, v, o);
            int   oi = __shfl_xor_sync(0xffffffffu, idx, o);
            if (ov > v || (ov == v && oi < idx)) { v = ov; idx = oi; }
        }
        if (lane == idx) sel = true;
    }
    unsigned ball = __ballot_sync(0xffffffffu, sel);
    if (sel) {
        int slot = __popc(ball & ((1u << lane) - 1u));
        g_kdst[n * KS + slot] = d;
        g_kw[n * KS + slot]   = score;
        float4 adv = *(const float4*)(g_ad + d * NH);
        float4 ex4;
        float lg;
        lg = as_s[0] + adv.x; lg = lg > 0.f ? lg : 0.2f * lg; ex4.x = expf(lg);
        lg = as_s[1] + adv.y; lg = lg > 0.f ? lg : 0.2f * lg; ex4.y = expf(lg);
        lg = as_s[2] + adv.z; lg = lg > 0.f ? lg : 0.2f * lg; ex4.z = expf(lg);
        lg = as_s[3] + adv.w; lg = lg > 0.f ? lg : 0.2f * lg; ex4.w = expf(lg);
        *(float4*)(g_kex + (n * KS + slot) * NH) = ex4;
        atomicAdd(&g_ssum[d * NH + 0], ex4.x);
        atomicAdd(&g_ssum[d * NH + 1], ex4.y);
        atomicAdd(&g_ssum[d * NH + 2], ex4.z);
        atomicAdd(&g_ssum[d * NH + 3], ex4.w);
    }
}

// ---------------- K3: alpha + row-normalize + dedup; save A slots; out messages ----------------
// grid = N/8 blocks, 256 threads (one warp per node).
__global__ void k4_mid(int step, float* __restrict__ outp) {
    int warp = threadIdx.x >> 5, lane = threadIdx.x & 31;
    int n = blockIdx.x * 8 + warp;
    const unsigned full = 0xffffffffu;
    int i = (lane >> 2) & 3, h = lane & 3;  // lanes 16..31 mirror 0..15

    int   d_i = g_kdst[n * KS + i];
    float w_i = g_kw[n * KS + i];
    float ex  = g_kex[(n * KS + i) * NH + h];
    float alpha = ex / fmaxf(g_ssum[d_i * NH + h], 1e-16f);

    // row sum over the 4 slots for this head
    float rs = alpha;
    rs += __shfl_xor_sync(full, rs, 4);
    rs += __shfl_xor_sync(full, rs, 8);
    float rinv = 1.f / fmaxf(rs, 1e-9f);

    // dedup: merge duplicate dst into the first slot
    bool first = true;
    float acc = alpha;
#pragma unroll
    for (int jj = 0; jj < KS; jj++) {
        int   dj = __shfl_sync(full, d_i,   jj * 4 + h);
        float aj = __shfl_sync(full, alpha, jj * 4 + h);
        if (jj < i && dj == d_i) first = false;
        if (jj > i && dj == d_i) acc += aj;
    }
    if (lane < 16) {
        g_Aval[(((size_t)step * NN + n) * KS + i) * NH + h] = first ? acc * rinv : 0.f;
        if (h == 0) g_Adst[((size_t)step * NN + n) * KS + i] = first ? d_i : -1;
    }

    // out messages: 32 lanes = 4 heads x 8 channels, loop over 4 edges
    int h2 = lane >> 3, c = lane & 7;
    float xhv = g_xh[n * EMB + h2 * CD + c];
#pragma unroll
    for (int jj = 0; jj < KS; jj++) {
        float a_jh = __shfl_sync(full, alpha, jj * 4 + h2);
        float wj   = __shfl_sync(full, w_i,   jj * 4);
        int   dj   = __shfl_sync(full, d_i,   jj * 4);
        atomicAdd(&outp[((size_t)step * NN + dj) * EMB + h2 * CD + c], a_jh * xhv * wj);
    }
}

// ---------------- final: stream-write all attention matrices (zeros + fold-in scatter) ----------------
// grid = BS*NH*NN blocks (one per row), 128 threads.
__global__ void writeA(float* __restrict__ outp) {
    int r  = blockIdx.x;              // ((st*NH + hh)*NN + n)
    int n  = r % NN;
    int hh = (r / NN) & 3;
    int st = r / (NN * NH);
    int base = (st * NN + n) * KS;

    int   ds[KS];
    float vs[KS];
#pragma unroll
    for (int i = 0; i < KS; i++) {
        ds[i] = g_Adst[base + i];
        vs[i] = (ds[i] >= 0) ? g_Aval[(base + i) * NH + hh] : 0.f;
    }

    float4* row4 = (float4*)(outp + ATTN_OFS + (size_t)r * NN);
    for (int idx = threadIdx.x; idx < NN / 4; idx += 128) {
        float4 v = make_float4(0.f, 0.f, 0.f, 0.f);
#pragma unroll
        for (int i = 0; i < KS; i++) {
            if (ds[i] >= 0 && (ds[i] >> 2) == idx) {
                int c = ds[i] & 3;
                if (c == 0) v.x += vs[i];
                else if (c == 1) v.y += vs[i];
                else if (c == 2) v.z += vs[i];
                else v.w += vs[i];
            }
        }
        row4[idx] = v;
    }
}

// ---------------- launch ----------------
extern "C" void kernel_launch(void* const* d_in, const int* in_sizes, int n_in,
                              void* d_out, int out_size) {
    int base = (in_sizes[3] == 1) ? 4 : 3;  // scalar k may or may not be materialized
    const float* Ht  = (const float*)d_in[0];
    const int*   dst = (const int*)d_in[2];
    const float* We1 = (const float*)d_in[base + 0];
    const float* be1 = (const float*)d_in[base + 1];
    const float* We2 = (const float*)d_in[base + 2];
    const float* be2 = (const float*)d_in[base + 3];
    const float* lng = (const float*)d_in[base + 4];
    const float* lnb = (const float*)d_in[base + 5];
    const float* Wih = (const float*)d_in[base + 6];
    const float* Whh = (const float*)d_in[base + 7];
    const float* bih = (const float*)d_in[base + 8];
    const float* bhh = (const float*)d_in[base + 9];
    const float* Ws1 = (const float*)d_in[base + 10];
    const float* bs1 = (const float*)d_in[base + 11];
    const float* Ws2 = (const float*)d_in[base + 12];
    const float* bs2 = (const float*)d_in[base + 13];
    const float* Wgat = (const float*)d_in[base + 14];
    const float* asrc = (const float*)d_in[base + 15];
    const float* adst = (const float*)d_in[base + 16];
    const float* bgat = (const float*)d_in[base + 17];
    float* outp = (float*)d_out;

    embed_k<<<(BS * NN) / RTB, 32>>>(Ht, We1, be1, We2, be2, lng, lnb);
    for (int t = 0; t < BS; t++) {
        k1_node<<<NN / NTB, 64>>>(t, Wih, Whh, bih, bhh, Ws1, bs1, Wgat, asrc, adst, bgat, outp);
        k2_edge<<<NN, 32>>>(dst, Ws2, bs2);
        k4_mid<<<NN / 8, 256>>>(t, outp);
    }
    writeA<<<BS * NH * NN, 128>>>(outp);
}